// round 12
// baseline (speedup 1.0000x reference)
#include <cuda_runtime.h>
#include <cstdint>

#define BB 16
#define FM 32
#define CC 128
#define HW 3136
#define ETA 0.1f
#define ALPHA_ 0.1f
#define THETA_ 0.1f
#define EPSF 1e-10f

typedef unsigned long long ull;

// ------------- scratch (static device globals; no allocation) -------------
__device__ float g_Ab[BB*CC*HW];        // clip(tile(symm_pad(A,2)) + eta*noise, 0)
__device__ float g_s[BB*CC];            // per-(b,c) spatial sum
__device__ float g_Kch[CC*CC*25];       // K_change [c][a][x*5+y]
__device__ float g_W2[CC*CC*25];        // conv2 weights [o][i][t]
__device__ float g_W3[BB*FM*25*FM];     // gathered weights [b][i][t][f]

// ---------------- packed f32x2 helpers ----------------
__device__ __forceinline__ ull pack2(float x, float y) {
    ull r; asm("mov.b64 %0, {%1,%2};" : "=l"(r) : "f"(x), "f"(y)); return r;
}
__device__ __forceinline__ void ffma2(ull& d, ull a, ull b) {
    asm("fma.rn.f32x2 %0, %1, %2, %3;" : "=l"(d) : "l"(a), "l"(b), "l"(d));
}
__device__ __forceinline__ float2 unpk(ull v) {
    float2 r; asm("mov.b64 {%0,%1}, %2;" : "=f"(r.x), "=f"(r.y) : "l"(v)); return r;
}

// symm_pad(.,2) index map on a 56 axis
__device__ __forceinline__ int m56(int h) {
    return h < 2 ? 3 - h : (h >= 54 ? 107 - h : h);
}
// pad_activations row/col map on the 60 axis
__device__ __forceinline__ int m60(int r) {
    return r < 4 ? 5 - r : (r < 56 ? r - 2 : 109 - r);
}

// ---------------- kernel 1: Ab + per-channel sums (+ zero g_Kch) -----------
__global__ void __launch_bounds__(224) k_prep(const float* __restrict__ A,
                                              const float* __restrict__ noise) {
    int bid = blockIdx.x;              // b*128 + c
    int tid = threadIdx.x;
    {
        int z0 = bid*200;
        if (tid < 200) g_Kch[z0 + tid] = 0.f;
    }
    int b = bid >> 7, c = bid & 127;
    int f = c & 31;
    const float* Ap = A + (size_t)(b*FM + f)*HW;
    const float* Np = noise + (size_t)bid*HW;
    float* Op = g_Ab + (size_t)bid*HW;

    int h0 = tid / 56, w0 = tid - (tid/56)*56;
    int mw = m56(w0);
    float sum = 0.f;
    #pragma unroll
    for (int j = 0; j < 14; j++) {
        int h = h0 + j*4;
        int idx = h*56 + w0;
        float v = fmaxf(Ap[m56(h)*56 + mw] + ETA*Np[idx], 0.f);
        Op[idx] = v;
        sum += v;
    }
    __shared__ float red[7];
    #pragma unroll
    for (int o = 16; o; o >>= 1) sum += __shfl_xor_sync(~0u, sum, o);
    if ((tid & 31) == 0) red[tid >> 5] = sum;
    __syncthreads();
    if (tid < 32) {
        float s2 = (tid < 7) ? red[tid] : 0.f;
        #pragma unroll
        for (int o = 4; o; o >>= 1) s2 += __shfl_xor_sync(0xffu, s2, o);
        if (tid == 0) g_s[bid] = s2;
    }
}

// ---------------- K_change (R8 version, best known) ------------------------
#define CHS 34
#define SAB_FLOATS (6*60*CHS)            // 12240
#define SAM_ULL (2*16*56)
#define SMEM_KCH (SAB_FLOATS*4 + SAM_ULL*8)   // 63296 B

__global__ void __launch_bounds__(256) k_kch() {
    int b = blockIdx.x, cwt = blockIdx.y, at = blockIdx.z;
    int tid = threadIdx.x;
    int lane = tid & 31, wid = tid >> 5;
    int al = lane & 15;
    int cl = wid*2 + (lane >> 4);
    int a0 = at*32;

    extern __shared__ char smraw[];
    float* sAb  = (float*)smraw;                      // [6][60][34]
    ull*   sAm2 = (ull*)(smraw + SAB_FLOATS*4);       // [2][16][56]
    __shared__ int sC[16];

    if (tid < 16) {
        int f = cwt*16 + tid;
        float best = g_s[b*CC + f]; int wr = 0;
        #pragma unroll
        for (int r = 1; r < 4; r++) {
            float v = g_s[b*CC + r*FM + f];
            if (v > best) { best = v; wr = r; }
        }
        sC[tid] = wr*FM + f;
    }
    for (int i = tid; i < SAB_FLOATS; i += 256) sAb[i] = 0.f;
    __syncthreads();

    const float* AbB = g_Ab + (size_t)b*CC*HW;

    for (int r = 0; r < 3; r++)
        for (int idx = tid; idx < 32*56; idx += 256) {
            int ch = idx / 56, col = idx - ch*56;
            sAb[(r*60 + col + 2)*CHS + ch] = AbB[(size_t)(a0+ch)*HW + r*56 + col];
        }
    for (int idx = tid; idx < 16*56; idx += 256) {
        int cj = idx / 56, col = idx - cj*56;
        float v = AbB[(size_t)sC[cj]*HW + col];
        sAm2[cj*56 + col] = pack2(v, v);
    }
    int myc = sC[cl];
    __syncthreads();

    ull acc[5][5];
    #pragma unroll
    for (int x = 0; x < 5; x++)
        #pragma unroll
        for (int y = 0; y < 5; y++) acc[x][y] = 0ull;

    for (int h = 0; h < 56; h++) {
        float pf[7];
        int prow = h + 3;
        bool pv = prow < 56;
        #pragma unroll
        for (int j = 0; j < 7; j++) {
            int idx = tid + j*256;
            int ch = idx / 56, col = idx - ch*56;
            pf[j] = pv ? AbB[(size_t)(a0+ch)*HW + prow*56 + col] : 0.f;
        }
        float pa[4];
        int arow = h + 1;
        #pragma unroll
        for (int j = 0; j < 4; j++) {
            int idx = tid + j*256;
            pa[j] = 0.f;
            if (arow < 56 && idx < 16*56) {
                int cj = idx / 56, co = idx - cj*56;
                pa[j] = AbB[(size_t)sC[cj]*HW + arow*56 + co];
            }
        }

        const char* rxp[5];
        #pragma unroll
        for (int x = 0; x < 5; x++) {
            int slot = (h + 8 - x) % 6;
            rxp[x] = (const char*)(sAb + slot*60*CHS + 2*al);
        }
        const ull* am = sAm2 + (size_t)(h & 1)*16*56 + cl*56;

        ull rg[5][5];
        #pragma unroll
        for (int x = 0; x < 5; x++)
            #pragma unroll
            for (int j = 0; j < 5; j++)
                rg[x][j] = *(const ull*)(rxp[x] + j*(CHS*4));

        #pragma unroll 1
        for (int wb = 0; wb < 55; wb += 5) {
            #pragma unroll
            for (int k = 0; k < 5; k++) {
                ull a = am[wb + k];
                #pragma unroll
                for (int x = 0; x < 5; x++) {
                    #pragma unroll
                    for (int y = 0; y < 5; y++)
                        ffma2(acc[x][y], a, rg[x][(k + 4 - y) % 5]);
                    rg[x][k] = *(const ull*)(rxp[x] + (wb + k + 5)*(CHS*4));
                }
            }
        }
        {
            ull a = am[55];
            #pragma unroll
            for (int x = 0; x < 5; x++)
                #pragma unroll
                for (int y = 0; y < 5; y++)
                    ffma2(acc[x][y], a, rg[x][(4 - y) % 5]);
        }

        {
            int slot = (h + 3) % 6;
            #pragma unroll
            for (int j = 0; j < 7; j++) {
                int idx = tid + j*256;
                int ch = idx / 56, col = idx - ch*56;
                sAb[(slot*60 + col + 2)*CHS + ch] = pf[j];
            }
            if (arow < 56) {
                ull* dst = sAm2 + (size_t)(arow & 1)*16*56;
                #pragma unroll
                for (int j = 0; j < 4; j++) {
                    int idx = tid + j*256;
                    if (idx < 16*56) {
                        int cj = idx / 56, co = idx - cj*56;
                        dst[cj*56 + co] = pack2(pa[j], pa[j]);
                    }
                }
            }
        }
        __syncthreads();
    }

    float* dst = g_Kch + ((size_t)myc*CC + (a0 + 2*al))*25;
    #pragma unroll
    for (int x = 0; x < 5; x++)
        #pragma unroll
        for (int y = 0; y < 5; y++) {
            float2 v = unpk(acc[x][y]);
            atomicAdd(&dst[x*5 + y],      v.x * (1.f/2048.f));
            atomicAdd(&dst[25 + x*5 + y], v.y * (1.f/2048.f));
        }
}

// ---------------- W2 = minmax(0.9*K1 + 0.1*minmax(K_change)) ---------------
__global__ void k_w2(const float* __restrict__ K) {
    int g = blockIdx.x*blockDim.x + threadIdx.x;
    if (g >= CC*CC) return;
    int o = g >> 7, i = g & 127;
    const float* kch = g_Kch + ((size_t)i*CC + o)*25;
    float v[25];
    float mn = 1e30f, mx = -1e30f;
    #pragma unroll
    for (int t = 0; t < 25; t++) { v[t] = kch[t]; mn = fminf(mn, v[t]); mx = fmaxf(mx, v[t]); }
    float inv = 1.f / (mx - mn + EPSF);
    const float* kk = K + ((size_t)o*CC + i)*25;   // K1[i][o] = K[o][i]
    float mn2 = 1e30f, mx2 = -1e30f;
    #pragma unroll
    for (int t = 0; t < 25; t++) {
        v[t] = (1.f - ALPHA_)*kk[t] + ALPHA_*((v[t] - mn)*inv);
        mn2 = fminf(mn2, v[t]); mx2 = fmaxf(mx2, v[t]);
    }
    float inv2 = 1.f / (mx2 - mn2 + EPSF);
    float* w = g_W2 + (size_t)g*25;
    #pragma unroll
    for (int t = 0; t < 25; t++) w[t] = (v[t] - mn2)*inv2;
}

// ---------------- gather winner weights: g_W3[b][i][t][f] ------------------
__global__ void __launch_bounds__(256) k_gw() {
    int b = blockIdx.x;
    int tid = threadIdx.x;
    __shared__ int sFm[32];
    if (tid < 32) {
        float best = g_s[b*CC + tid]; int wr = 0;
        #pragma unroll
        for (int r = 1; r < 4; r++) {
            float v = g_s[b*CC + r*FM + tid];
            if (v > best) { best = v; wr = r; }
        }
        sFm[tid] = wr*FM + tid;
    }
    __syncthreads();
    float* W3b = g_W3 + (size_t)b*FM*25*FM;
    for (int idx = tid; idx < 32*25*32; idx += 256) {
        int i = idx / 800, rem = idx - i*800;
        int t = rem >> 5, f = rem & 31;
        W3b[idx] = g_W2[((size_t)sFm[f]*CC + sFm[i])*25 + t];
    }
}

// ---------------- k_out v4: 16 warps/SM, weights via L2 --------------------
// grid (b=16, pc=7) = 112 blocks; 512 threads = 2 i-halves x (8 rows x 32 lanes)
// lane = 16 f-pairs x 2 q-groups; acc[j] = {out[q0+j], out[q0+28+j]}
#define SP_ULL   (12*32*32)            // 12288
#define SRED_ULL (256*28)              // 7168
#define SMEM_OUT ((SP_ULL + SRED_ULL)*8)   // 155648 B

__global__ void __launch_bounds__(512) k_out(float* __restrict__ out) {
    int b = blockIdx.x, pc = blockIdx.y;   // pc 0..6
    int p0 = pc * 8;
    int tid = threadIdx.x;
    int half = tid >> 8;               // i-half: i in [16*half, 16*half+16)
    int t8 = tid & 255;
    int pl = t8 >> 5;                  // local output row 0..7
    int lane = t8 & 31;
    int fp = lane & 15;                // f-pair -> f = 2fp, 2fp+1
    int qg = lane >> 4;                // 0,1
    int q0 = qg * 14;

    extern __shared__ ull sh[];
    ull* sP   = sh;                    // [12][32][32] {v[c], v[c+28]}
    ull* sRed = sh + SP_ULL;           // [256][28] partials from half=1
    __shared__ int sFm[32];
    if (tid < 32) {
        float best = g_s[b*CC + tid]; int wr = 0;
        #pragma unroll
        for (int r = 1; r < 4; r++) {
            float v = g_s[b*CC + r*FM + tid];
            if (v > best) { best = v; wr = r; }
        }
        sFm[tid] = wr*FM + tid;
    }
    __syncthreads();

    const float* AbB = g_Ab + (size_t)b*CC*HW;
    // sP fill: 12 padded rows, strided pairs
    for (int idx = tid; idx < 12*32*32; idx += 512) {
        int r = idx >> 10;             // /1024
        int rem = idx & 1023;
        int i = rem >> 5, c = rem & 31;
        int sr = m60(p0 + r);
        const float* src = AbB + (size_t)sFm[i]*HW + sr*56;
        sP[idx] = pack2(src[m60(c)], src[m60(c + 28)]);
    }
    __syncthreads();

    ull acc[2][14];
    #pragma unroll
    for (int ff = 0; ff < 2; ff++)
        #pragma unroll
        for (int j = 0; j < 14; j++) acc[ff][j] = 0ull;

    const float* W3b = g_W3 + (size_t)b*FM*25*FM + 2*fp;
    int i0 = half*16;

    #pragma unroll 1
    for (int i = i0; i < i0 + 16; i++) {
        #pragma unroll
        for (int u = 0; u < 5; u++) {
            const ull* vp = sP + (size_t)((pl + u)*32 + i)*32 + q0;
            ull v[18];
            #pragma unroll
            for (int k = 0; k < 9; k++) {
                ulonglong2 t2 = *(const ulonglong2*)(vp + 2*k);
                v[2*k] = t2.x; v[2*k+1] = t2.y;
            }
            const float* wr = W3b + (i*25 + u*5)*32;
            #pragma unroll
            for (int y = 0; y < 5; y++) {
                float2 wf = *(const float2*)(wr + y*32);
                ull w0 = pack2(wf.x, wf.x), w1 = pack2(wf.y, wf.y);
                #pragma unroll
                for (int j = 0; j < 14; j++) {
                    ffma2(acc[0][j], v[j + y], w0);
                    ffma2(acc[1][j], v[j + y], w1);
                }
            }
        }
    }

    // half 1 hands its partials to half 0
    if (half == 1) {
        ull* red = sRed + (size_t)t8*28;
        #pragma unroll
        for (int ff = 0; ff < 2; ff++)
            #pragma unroll
            for (int j = 0; j < 14; j++) red[ff*14 + j] = acc[ff][j];
    }
    __syncthreads();
    if (half == 0) {
        const ull* red = sRed + (size_t)t8*28;
        int p = p0 + pl;
        #pragma unroll
        for (int ff = 0; ff < 2; ff++) {
            int f = 2*fp + ff;
            const float* ar = AbB + (size_t)sFm[f]*HW + p*56;
            float* orow = out + ((size_t)(b*FM + f)*56 + p)*56;
            #pragma unroll
            for (int j = 0; j < 14; j++) {
                float2 vv = unpk(acc[ff][j]);
                float2 rr = unpk(red[ff*14 + j]);
                vv.x += rr.x; vv.y += rr.y;
                orow[q0 + j]      = ar[q0 + j]      + THETA_ * (vv.x * (1.f/32.f));
                orow[q0 + 28 + j] = ar[q0 + 28 + j] + THETA_ * (vv.y * (1.f/32.f));
            }
        }
    }
}

// ---------------- launch ----------------
extern "C" void kernel_launch(void* const* d_in, const int* in_sizes, int n_in,
                              void* d_out, int out_size) {
    const float* A     = (const float*)d_in[0];
    const float* K     = (const float*)d_in[1];
    const float* noise = (const float*)d_in[2];
    float* out = (float*)d_out;

    k_prep<<<BB*CC, 224>>>(A, noise);

    cudaFuncSetAttribute(k_kch, cudaFuncAttributeMaxDynamicSharedMemorySize, SMEM_KCH);
    k_kch<<<dim3(BB, 2, 4), 256, SMEM_KCH>>>();

    k_w2<<<128, 128>>>(K);
    k_gw<<<BB, 256>>>();

    cudaFuncSetAttribute(k_out, cudaFuncAttributeMaxDynamicSharedMemorySize, SMEM_OUT);
    k_out<<<dim3(BB, 7), 512, SMEM_OUT>>>(out);
}

// round 13
// speedup vs baseline: 1.0322x; 1.0322x over previous
#include <cuda_runtime.h>
#include <cstdint>

#define BB 16
#define FM 32
#define CC 128
#define HW 3136
#define ETA 0.1f
#define ALPHA_ 0.1f
#define THETA_ 0.1f
#define EPSF 1e-10f

typedef unsigned long long ull;

// ------------- scratch (static device globals; no allocation) -------------
__device__ float g_Ab[BB*CC*HW];        // clip(tile(symm_pad(A,2)) + eta*noise, 0)
__device__ float g_s[BB*CC];            // per-(b,c) spatial sum
__device__ float g_Kch[CC*CC*25];       // K_change [c][a][x*5+y]
__device__ float g_W2[CC*CC*25];        // conv2 weights [o][i][t]
__device__ float g_W3[BB*FM*25*FM];     // gathered weights [b][i][t][f]

// ---------------- packed f32x2 helpers ----------------
__device__ __forceinline__ ull pack2(float x, float y) {
    ull r; asm("mov.b64 %0, {%1,%2};" : "=l"(r) : "f"(x), "f"(y)); return r;
}
__device__ __forceinline__ void ffma2(ull& d, ull a, ull b) {
    asm("fma.rn.f32x2 %0, %1, %2, %3;" : "=l"(d) : "l"(a), "l"(b), "l"(d));
}
__device__ __forceinline__ float2 unpk(ull v) {
    float2 r; asm("mov.b64 {%0,%1}, %2;" : "=f"(r.x), "=f"(r.y) : "l"(v)); return r;
}

// symm_pad(.,2) index map on a 56 axis
__device__ __forceinline__ int m56(int h) {
    return h < 2 ? 3 - h : (h >= 54 ? 107 - h : h);
}
// pad_activations row/col map on the 60 axis
__device__ __forceinline__ int m60(int r) {
    return r < 4 ? 5 - r : (r < 56 ? r - 2 : 109 - r);
}
// inline winner for channel f of batch b
__device__ __forceinline__ int winner(int b, int f) {
    float best = g_s[b*CC + f]; int wr = 0;
    #pragma unroll
    for (int r = 1; r < 4; r++) {
        float v = g_s[b*CC + r*FM + f];
        if (v > best) { best = v; wr = r; }
    }
    return wr*FM + f;
}

// ---------------- kernel 1: Ab + per-channel sums (+ zero g_Kch) -----------
__global__ void __launch_bounds__(224) k_prep(const float* __restrict__ A,
                                              const float* __restrict__ noise) {
    int bid = blockIdx.x;              // b*128 + c
    int tid = threadIdx.x;
    {
        int z0 = bid*200;
        if (tid < 200) g_Kch[z0 + tid] = 0.f;
    }
    int b = bid >> 7, c = bid & 127;
    int f = c & 31;
    const float* Ap = A + (size_t)(b*FM + f)*HW;
    const float* Np = noise + (size_t)bid*HW;
    float* Op = g_Ab + (size_t)bid*HW;

    int h0 = tid / 56, w0 = tid - (tid/56)*56;
    int mw = m56(w0);
    float sum = 0.f;
    #pragma unroll
    for (int j = 0; j < 14; j++) {
        int h = h0 + j*4;
        int idx = h*56 + w0;
        float v = fmaxf(Ap[m56(h)*56 + mw] + ETA*Np[idx], 0.f);
        Op[idx] = v;
        sum += v;
    }
    __shared__ float red[7];
    #pragma unroll
    for (int o = 16; o; o >>= 1) sum += __shfl_xor_sync(~0u, sum, o);
    if ((tid & 31) == 0) red[tid >> 5] = sum;
    __syncthreads();
    if (tid < 32) {
        float s2 = (tid < 7) ? red[tid] : 0.f;
        #pragma unroll
        for (int o = 4; o; o >>= 1) s2 += __shfl_xor_sync(0xffu, s2, o);
        if (tid == 0) g_s[bid] = s2;
    }
}

// ---------------- K_change (R8 version, best known) ------------------------
#define CHS 34
#define SAB_FLOATS (6*60*CHS)            // 12240
#define SAM_ULL (2*16*56)
#define SMEM_KCH (SAB_FLOATS*4 + SAM_ULL*8)   // 63296 B

__global__ void __launch_bounds__(256) k_kch() {
    int b = blockIdx.x, cwt = blockIdx.y, at = blockIdx.z;
    int tid = threadIdx.x;
    int lane = tid & 31, wid = tid >> 5;
    int al = lane & 15;
    int cl = wid*2 + (lane >> 4);
    int a0 = at*32;

    extern __shared__ char smraw[];
    float* sAb  = (float*)smraw;                      // [6][60][34]
    ull*   sAm2 = (ull*)(smraw + SAB_FLOATS*4);       // [2][16][56]
    __shared__ int sC[16];

    if (tid < 16) sC[tid] = winner(b, cwt*16 + tid);
    for (int i = tid; i < SAB_FLOATS; i += 256) sAb[i] = 0.f;
    __syncthreads();

    const float* AbB = g_Ab + (size_t)b*CC*HW;

    for (int r = 0; r < 3; r++)
        for (int idx = tid; idx < 32*56; idx += 256) {
            int ch = idx / 56, col = idx - ch*56;
            sAb[(r*60 + col + 2)*CHS + ch] = AbB[(size_t)(a0+ch)*HW + r*56 + col];
        }
    for (int idx = tid; idx < 16*56; idx += 256) {
        int cj = idx / 56, col = idx - cj*56;
        float v = AbB[(size_t)sC[cj]*HW + col];
        sAm2[cj*56 + col] = pack2(v, v);
    }
    int myc = sC[cl];
    __syncthreads();

    ull acc[5][5];
    #pragma unroll
    for (int x = 0; x < 5; x++)
        #pragma unroll
        for (int y = 0; y < 5; y++) acc[x][y] = 0ull;

    for (int h = 0; h < 56; h++) {
        float pf[7];
        int prow = h + 3;
        bool pv = prow < 56;
        #pragma unroll
        for (int j = 0; j < 7; j++) {
            int idx = tid + j*256;
            int ch = idx / 56, col = idx - ch*56;
            pf[j] = pv ? AbB[(size_t)(a0+ch)*HW + prow*56 + col] : 0.f;
        }
        float pa[4];
        int arow = h + 1;
        #pragma unroll
        for (int j = 0; j < 4; j++) {
            int idx = tid + j*256;
            pa[j] = 0.f;
            if (arow < 56 && idx < 16*56) {
                int cj = idx / 56, co = idx - cj*56;
                pa[j] = AbB[(size_t)sC[cj]*HW + arow*56 + co];
            }
        }

        const char* rxp[5];
        #pragma unroll
        for (int x = 0; x < 5; x++) {
            int slot = (h + 8 - x) % 6;
            rxp[x] = (const char*)(sAb + slot*60*CHS + 2*al);
        }
        const ull* am = sAm2 + (size_t)(h & 1)*16*56 + cl*56;

        ull rg[5][5];
        #pragma unroll
        for (int x = 0; x < 5; x++)
            #pragma unroll
            for (int j = 0; j < 5; j++)
                rg[x][j] = *(const ull*)(rxp[x] + j*(CHS*4));

        #pragma unroll 1
        for (int wb = 0; wb < 55; wb += 5) {
            #pragma unroll
            for (int k = 0; k < 5; k++) {
                ull a = am[wb + k];
                #pragma unroll
                for (int x = 0; x < 5; x++) {
                    #pragma unroll
                    for (int y = 0; y < 5; y++)
                        ffma2(acc[x][y], a, rg[x][(k + 4 - y) % 5]);
                    rg[x][k] = *(const ull*)(rxp[x] + (wb + k + 5)*(CHS*4));
                }
            }
        }
        {
            ull a = am[55];
            #pragma unroll
            for (int x = 0; x < 5; x++)
                #pragma unroll
                for (int y = 0; y < 5; y++)
                    ffma2(acc[x][y], a, rg[x][(4 - y) % 5]);
        }

        {
            int slot = (h + 3) % 6;
            #pragma unroll
            for (int j = 0; j < 7; j++) {
                int idx = tid + j*256;
                int ch = idx / 56, col = idx - ch*56;
                sAb[(slot*60 + col + 2)*CHS + ch] = pf[j];
            }
            if (arow < 56) {
                ull* dst = sAm2 + (size_t)(arow & 1)*16*56;
                #pragma unroll
                for (int j = 0; j < 4; j++) {
                    int idx = tid + j*256;
                    if (idx < 16*56) {
                        int cj = idx / 56, co = idx - cj*56;
                        dst[cj*56 + co] = pack2(pa[j], pa[j]);
                    }
                }
            }
        }
        __syncthreads();
    }

    float* dst = g_Kch + ((size_t)myc*CC + (a0 + 2*al))*25;
    #pragma unroll
    for (int x = 0; x < 5; x++)
        #pragma unroll
        for (int y = 0; y < 5; y++) {
            float2 v = unpk(acc[x][y]);
            atomicAdd(&dst[x*5 + y],      v.x * (1.f/2048.f));
            atomicAdd(&dst[25 + x*5 + y], v.y * (1.f/2048.f));
        }
}

// ---------------- W2 = minmax(0.9*K1 + 0.1*minmax(K_change)) ---------------
__global__ void k_w2(const float* __restrict__ K) {
    int g = blockIdx.x*blockDim.x + threadIdx.x;
    if (g >= CC*CC) return;
    int o = g >> 7, i = g & 127;
    const float* kch = g_Kch + ((size_t)i*CC + o)*25;
    float v[25];
    float mn = 1e30f, mx = -1e30f;
    #pragma unroll
    for (int t = 0; t < 25; t++) { v[t] = kch[t]; mn = fminf(mn, v[t]); mx = fmaxf(mx, v[t]); }
    float inv = 1.f / (mx - mn + EPSF);
    const float* kk = K + ((size_t)o*CC + i)*25;   // K1[i][o] = K[o][i]
    float mn2 = 1e30f, mx2 = -1e30f;
    #pragma unroll
    for (int t = 0; t < 25; t++) {
        v[t] = (1.f - ALPHA_)*kk[t] + ALPHA_*((v[t] - mn)*inv);
        mn2 = fminf(mn2, v[t]); mx2 = fmaxf(mx2, v[t]);
    }
    float inv2 = 1.f / (mx2 - mn2 + EPSF);
    float* w = g_W2 + (size_t)g*25;
    #pragma unroll
    for (int t = 0; t < 25; t++) w[t] = (v[t] - mn2)*inv2;
}

// ---------------- gather winner weights: g_W3[b][i][t][f], 1 elem/thread ---
// grid (100, 16) x 256 threads = 409600 threads (full parallel gather)
__global__ void __launch_bounds__(256) k_gw() {
    int b = blockIdx.y;
    int idx = blockIdx.x*256 + threadIdx.x;     // 0..25599
    int i = idx / 800, rem = idx - i*800;
    int f = rem & 31, t = rem >> 5;
    int wf = winner(b, f), wi = winner(b, i);
    g_W3[(size_t)b*FM*25*FM + idx] = g_W2[((size_t)wf*CC + wi)*25 + t];
}

// ---------------- k_out v4: 16 warps/SM, weights via L2 --------------------
// grid (b=16, pc=7) = 112 blocks; 512 threads = 2 i-halves x (8 rows x 32 lanes)
// lane = 16 f-pairs x 2 q-groups; acc[j] = {out[q0+j], out[q0+28+j]}
#define SP_ULL   (12*32*32)            // 12288
#define SRED_ULL (256*28)              // 7168
#define SMEM_OUT ((SP_ULL + SRED_ULL)*8)   // 155648 B

__global__ void __launch_bounds__(512) k_out(float* __restrict__ out) {
    int b = blockIdx.x, pc = blockIdx.y;   // pc 0..6
    int p0 = pc * 8;
    int tid = threadIdx.x;
    int half = tid >> 8;               // i-half: i in [16*half, 16*half+16)
    int t8 = tid & 255;
    int pl = t8 >> 5;                  // local output row 0..7
    int lane = t8 & 31;
    int fp = lane & 15;                // f-pair -> f = 2fp, 2fp+1
    int qg = lane >> 4;                // 0,1
    int q0 = qg * 14;

    extern __shared__ ull sh[];
    ull* sP   = sh;                    // [12][32][32] {v[c], v[c+28]}
    ull* sRed = sh + SP_ULL;           // [256][28] partials from half=1
    __shared__ int sFm[32];
    if (tid < 32) sFm[tid] = winner(b, tid);
    __syncthreads();

    const float* AbB = g_Ab + (size_t)b*CC*HW;
    // sP fill: 12 padded rows, strided pairs
    for (int idx = tid; idx < 12*32*32; idx += 512) {
        int r = idx >> 10;             // /1024
        int rem = idx & 1023;
        int i = rem >> 5, c = rem & 31;
        int sr = m60(p0 + r);
        const float* src = AbB + (size_t)sFm[i]*HW + sr*56;
        sP[idx] = pack2(src[m60(c)], src[m60(c + 28)]);
    }
    __syncthreads();

    ull acc[2][14];
    #pragma unroll
    for (int ff = 0; ff < 2; ff++)
        #pragma unroll
        for (int j = 0; j < 14; j++) acc[ff][j] = 0ull;

    const float* W3b = g_W3 + (size_t)b*FM*25*FM + 2*fp;
    int i0 = half*16;

    #pragma unroll 1
    for (int i = i0; i < i0 + 16; i++) {
        #pragma unroll
        for (int u = 0; u < 5; u++) {
            const ull* vp = sP + (size_t)((pl + u)*32 + i)*32 + q0;
            ull v[18];
            #pragma unroll
            for (int k = 0; k < 9; k++) {
                ulonglong2 t2 = *(const ulonglong2*)(vp + 2*k);
                v[2*k] = t2.x; v[2*k+1] = t2.y;
            }
            const float* wr = W3b + (i*25 + u*5)*32;
            #pragma unroll
            for (int y = 0; y < 5; y++) {
                float2 wf = *(const float2*)(wr + y*32);
                ull w0 = pack2(wf.x, wf.x), w1 = pack2(wf.y, wf.y);
                #pragma unroll
                for (int j = 0; j < 14; j++) {
                    ffma2(acc[0][j], v[j + y], w0);
                    ffma2(acc[1][j], v[j + y], w1);
                }
            }
        }
    }

    // half 1 hands its partials to half 0
    if (half == 1) {
        ull* red = sRed + (size_t)t8*28;
        #pragma unroll
        for (int ff = 0; ff < 2; ff++)
            #pragma unroll
            for (int j = 0; j < 14; j++) red[ff*14 + j] = acc[ff][j];
    }
    __syncthreads();
    if (half == 0) {
        const ull* red = sRed + (size_t)t8*28;
        int p = p0 + pl;
        #pragma unroll
        for (int ff = 0; ff < 2; ff++) {
            int f = 2*fp + ff;
            const float* ar = AbB + (size_t)sFm[f]*HW + p*56;
            float* orow = out + ((size_t)(b*FM + f)*56 + p)*56;
            #pragma unroll
            for (int j = 0; j < 14; j++) {
                float2 vv = unpk(acc[ff][j]);
                float2 rr = unpk(red[ff*14 + j]);
                vv.x += rr.x; vv.y += rr.y;
                orow[q0 + j]      = ar[q0 + j]      + THETA_ * (vv.x * (1.f/32.f));
                orow[q0 + 28 + j] = ar[q0 + 28 + j] + THETA_ * (vv.y * (1.f/32.f));
            }
        }
    }
}

// ---------------- launch ----------------
extern "C" void kernel_launch(void* const* d_in, const int* in_sizes, int n_in,
                              void* d_out, int out_size) {
    const float* A     = (const float*)d_in[0];
    const float* K     = (const float*)d_in[1];
    const float* noise = (const float*)d_in[2];
    float* out = (float*)d_out;

    k_prep<<<BB*CC, 224>>>(A, noise);

    cudaFuncSetAttribute(k_kch, cudaFuncAttributeMaxDynamicSharedMemorySize, SMEM_KCH);
    k_kch<<<dim3(BB, 2, 4), 256, SMEM_KCH>>>();

    k_w2<<<128, 128>>>(K);
    k_gw<<<dim3(100, BB), 256>>>();

    cudaFuncSetAttribute(k_out, cudaFuncAttributeMaxDynamicSharedMemorySize, SMEM_OUT);
    k_out<<<dim3(BB, 7), 512, SMEM_OUT>>>(out);
}

// round 14
// speedup vs baseline: 1.0958x; 1.0616x over previous
#include <cuda_runtime.h>
#include <cstdint>

#define BB 16
#define FM 32
#define CC 128
#define HW 3136
#define ETA 0.1f
#define ALPHA_ 0.1f
#define THETA_ 0.1f
#define EPSF 1e-10f

typedef unsigned long long ull;

// ------------- scratch (static device globals; no allocation) -------------
__device__ float g_Ab[BB*CC*HW];        // clip(tile(symm_pad(A,2)) + eta*noise, 0)
__device__ float g_s[BB*CC];            // per-(b,c) spatial sum
__device__ float g_Kch[CC*CC*25];       // K_change [c][a][x*5+y]
__device__ float g_W2[CC*CC*25];        // conv2 weights [o][i][t]
__device__ float g_W3[BB*FM*5*16*12];   // gathered weights [b][i*5+u][fp][12]

// ---------------- packed f32x2 helpers ----------------
__device__ __forceinline__ ull pack2(float x, float y) {
    ull r; asm("mov.b64 %0, {%1,%2};" : "=l"(r) : "f"(x), "f"(y)); return r;
}
__device__ __forceinline__ void ffma2(ull& d, ull a, ull b) {
    asm("fma.rn.f32x2 %0, %1, %2, %3;" : "=l"(d) : "l"(a), "l"(b), "l"(d));
}
__device__ __forceinline__ float2 unpk(ull v) {
    float2 r; asm("mov.b64 {%0,%1}, %2;" : "=f"(r.x), "=f"(r.y) : "l"(v)); return r;
}

// symm_pad(.,2) index map on a 56 axis
__device__ __forceinline__ int m56(int h) {
    return h < 2 ? 3 - h : (h >= 54 ? 107 - h : h);
}
// pad_activations row/col map on the 60 axis
__device__ __forceinline__ int m60(int r) {
    return r < 4 ? 5 - r : (r < 56 ? r - 2 : 109 - r);
}
// inline winner for channel f of batch b
__device__ __forceinline__ int winner(int b, int f) {
    float best = g_s[b*CC + f]; int wr = 0;
    #pragma unroll
    for (int r = 1; r < 4; r++) {
        float v = g_s[b*CC + r*FM + f];
        if (v > best) { best = v; wr = r; }
    }
    return wr*FM + f;
}

// ---------------- kernel 1: Ab + per-channel sums (+ zero g_Kch) -----------
__global__ void __launch_bounds__(224) k_prep(const float* __restrict__ A,
                                              const float* __restrict__ noise) {
    int bid = blockIdx.x;              // b*128 + c
    int tid = threadIdx.x;
    {
        int z0 = bid*200;
        if (tid < 200) g_Kch[z0 + tid] = 0.f;
    }
    int b = bid >> 7, c = bid & 127;
    int f = c & 31;
    const float* Ap = A + (size_t)(b*FM + f)*HW;
    const float* Np = noise + (size_t)bid*HW;
    float* Op = g_Ab + (size_t)bid*HW;

    int h0 = tid / 56, w0 = tid - (tid/56)*56;
    int mw = m56(w0);
    float sum = 0.f;
    #pragma unroll
    for (int j = 0; j < 14; j++) {
        int h = h0 + j*4;
        int idx = h*56 + w0;
        float v = fmaxf(Ap[m56(h)*56 + mw] + ETA*Np[idx], 0.f);
        Op[idx] = v;
        sum += v;
    }
    __shared__ float red[7];
    #pragma unroll
    for (int o = 16; o; o >>= 1) sum += __shfl_xor_sync(~0u, sum, o);
    if ((tid & 31) == 0) red[tid >> 5] = sum;
    __syncthreads();
    if (tid < 32) {
        float s2 = (tid < 7) ? red[tid] : 0.f;
        #pragma unroll
        for (int o = 4; o; o >>= 1) s2 += __shfl_xor_sync(0xffu, s2, o);
        if (tid == 0) g_s[bid] = s2;
    }
}

// ---------------- K_change (R8 version, best known) ------------------------
#define CHS 34
#define SAB_FLOATS (6*60*CHS)            // 12240
#define SAM_ULL (2*16*56)
#define SMEM_KCH (SAB_FLOATS*4 + SAM_ULL*8)   // 63296 B

__global__ void __launch_bounds__(256) k_kch() {
    int b = blockIdx.x, cwt = blockIdx.y, at = blockIdx.z;
    int tid = threadIdx.x;
    int lane = tid & 31, wid = tid >> 5;
    int al = lane & 15;
    int cl = wid*2 + (lane >> 4);
    int a0 = at*32;

    extern __shared__ char smraw[];
    float* sAb  = (float*)smraw;                      // [6][60][34]
    ull*   sAm2 = (ull*)(smraw + SAB_FLOATS*4);       // [2][16][56]
    __shared__ int sC[16];

    if (tid < 16) sC[tid] = winner(b, cwt*16 + tid);
    for (int i = tid; i < SAB_FLOATS; i += 256) sAb[i] = 0.f;
    __syncthreads();

    const float* AbB = g_Ab + (size_t)b*CC*HW;

    for (int r = 0; r < 3; r++)
        for (int idx = tid; idx < 32*56; idx += 256) {
            int ch = idx / 56, col = idx - ch*56;
            sAb[(r*60 + col + 2)*CHS + ch] = AbB[(size_t)(a0+ch)*HW + r*56 + col];
        }
    for (int idx = tid; idx < 16*56; idx += 256) {
        int cj = idx / 56, col = idx - cj*56;
        float v = AbB[(size_t)sC[cj]*HW + col];
        sAm2[cj*56 + col] = pack2(v, v);
    }
    int myc = sC[cl];
    __syncthreads();

    ull acc[5][5];
    #pragma unroll
    for (int x = 0; x < 5; x++)
        #pragma unroll
        for (int y = 0; y < 5; y++) acc[x][y] = 0ull;

    for (int h = 0; h < 56; h++) {
        float pf[7];
        int prow = h + 3;
        bool pv = prow < 56;
        #pragma unroll
        for (int j = 0; j < 7; j++) {
            int idx = tid + j*256;
            int ch = idx / 56, col = idx - ch*56;
            pf[j] = pv ? AbB[(size_t)(a0+ch)*HW + prow*56 + col] : 0.f;
        }
        float pa[4];
        int arow = h + 1;
        #pragma unroll
        for (int j = 0; j < 4; j++) {
            int idx = tid + j*256;
            pa[j] = 0.f;
            if (arow < 56 && idx < 16*56) {
                int cj = idx / 56, co = idx - cj*56;
                pa[j] = AbB[(size_t)sC[cj]*HW + arow*56 + co];
            }
        }

        const char* rxp[5];
        #pragma unroll
        for (int x = 0; x < 5; x++) {
            int slot = (h + 8 - x) % 6;
            rxp[x] = (const char*)(sAb + slot*60*CHS + 2*al);
        }
        const ull* am = sAm2 + (size_t)(h & 1)*16*56 + cl*56;

        ull rg[5][5];
        #pragma unroll
        for (int x = 0; x < 5; x++)
            #pragma unroll
            for (int j = 0; j < 5; j++)
                rg[x][j] = *(const ull*)(rxp[x] + j*(CHS*4));

        #pragma unroll 1
        for (int wb = 0; wb < 55; wb += 5) {
            #pragma unroll
            for (int k = 0; k < 5; k++) {
                ull a = am[wb + k];
                #pragma unroll
                for (int x = 0; x < 5; x++) {
                    #pragma unroll
                    for (int y = 0; y < 5; y++)
                        ffma2(acc[x][y], a, rg[x][(k + 4 - y) % 5]);
                    rg[x][k] = *(const ull*)(rxp[x] + (wb + k + 5)*(CHS*4));
                }
            }
        }
        {
            ull a = am[55];
            #pragma unroll
            for (int x = 0; x < 5; x++)
                #pragma unroll
                for (int y = 0; y < 5; y++)
                    ffma2(acc[x][y], a, rg[x][(4 - y) % 5]);
        }

        {
            int slot = (h + 3) % 6;
            #pragma unroll
            for (int j = 0; j < 7; j++) {
                int idx = tid + j*256;
                int ch = idx / 56, col = idx - ch*56;
                sAb[(slot*60 + col + 2)*CHS + ch] = pf[j];
            }
            if (arow < 56) {
                ull* dst = sAm2 + (size_t)(arow & 1)*16*56;
                #pragma unroll
                for (int j = 0; j < 4; j++) {
                    int idx = tid + j*256;
                    if (idx < 16*56) {
                        int cj = idx / 56, co = idx - cj*56;
                        dst[cj*56 + co] = pack2(pa[j], pa[j]);
                    }
                }
            }
        }
        __syncthreads();
    }

    float* dst = g_Kch + ((size_t)myc*CC + (a0 + 2*al))*25;
    #pragma unroll
    for (int x = 0; x < 5; x++)
        #pragma unroll
        for (int y = 0; y < 5; y++) {
            float2 v = unpk(acc[x][y]);
            atomicAdd(&dst[x*5 + y],      v.x * (1.f/2048.f));
            atomicAdd(&dst[25 + x*5 + y], v.y * (1.f/2048.f));
        }
}

// ---------------- W2 = minmax(0.9*K1 + 0.1*minmax(K_change)) ---------------
__global__ void k_w2(const float* __restrict__ K) {
    int g = blockIdx.x*blockDim.x + threadIdx.x;
    if (g >= CC*CC) return;
    int o = g >> 7, i = g & 127;
    const float* kch = g_Kch + ((size_t)i*CC + o)*25;
    float v[25];
    float mn = 1e30f, mx = -1e30f;
    #pragma unroll
    for (int t = 0; t < 25; t++) { v[t] = kch[t]; mn = fminf(mn, v[t]); mx = fmaxf(mx, v[t]); }
    float inv = 1.f / (mx - mn + EPSF);
    const float* kk = K + ((size_t)o*CC + i)*25;   // K1[i][o] = K[o][i]
    float mn2 = 1e30f, mx2 = -1e30f;
    #pragma unroll
    for (int t = 0; t < 25; t++) {
        v[t] = (1.f - ALPHA_)*kk[t] + ALPHA_*((v[t] - mn)*inv);
        mn2 = fminf(mn2, v[t]); mx2 = fmaxf(mx2, v[t]);
    }
    float inv2 = 1.f / (mx2 - mn2 + EPSF);
    float* w = g_W2 + (size_t)g*25;
    #pragma unroll
    for (int t = 0; t < 25; t++) w[t] = (v[t] - mn2)*inv2;
}

// ------- gather winner weights: g_W3[b][i*5+u][fp][12], 1 elem/thread ------
// grid (120, 16) x 256 = 30720 threads per b-plane
__global__ void __launch_bounds__(256) k_gw() {
    int b = blockIdx.y;
    int idx = blockIdx.x*256 + threadIdx.x;     // 0..30719
    int k = idx % 12;
    int r = idx / 12;                           // iu*16 + fp
    int fp = r & 15;
    int iu = r >> 4;                            // i*5 + u
    int i = iu / 5, u = iu - i*5;
    float val = 0.f;
    if (k < 10) {
        int f = 2*fp + (k >= 5 ? 1 : 0);
        int y = (k >= 5) ? (k - 5) : k;
        int wf = winner(b, f), wi = winner(b, i);
        val = g_W2[((size_t)wf*CC + wi)*25 + u*5 + y];
    }
    g_W3[(size_t)b*30720 + idx] = val;
}

// ---------------- k_out v5: LDG-pipelined weights, 16 warps/SM -------------
// grid (b=16, pc=7) = 112 blocks; 512 threads = 2 i-halves x (8 rows x 32 lanes)
// lane = 16 f-pairs x 2 q-groups; acc[j] = {out[q0+j], out[q0+28+j]}
#define SP_ULL   (12*32*32)            // 12288
#define SRED_ULL (256*28)              // 7168
#define SMEM_OUT ((SP_ULL + SRED_ULL)*8)   // 155648 B

__global__ void __launch_bounds__(512) k_out(float* __restrict__ out) {
    int b = blockIdx.x, pc = blockIdx.y;   // pc 0..6
    int p0 = pc * 8;
    int tid = threadIdx.x;
    int half = tid >> 8;               // i-half: i in [16*half, 16*half+16)
    int t8 = tid & 255;
    int pl = t8 >> 5;                  // local output row 0..7
    int lane = t8 & 31;
    int fp = lane & 15;                // f-pair -> f = 2fp, 2fp+1
    int qg = lane >> 4;                // 0,1
    int q0 = qg * 14;

    extern __shared__ ull sh[];
    ull* sP   = sh;                    // [12][32][32] {v[c], v[c+28]}
    ull* sRed = sh + SP_ULL;           // [256][28] partials from half=1
    __shared__ int sFm[32];
    if (tid < 32) sFm[tid] = winner(b, tid);
    __syncthreads();

    const float* AbB = g_Ab + (size_t)b*CC*HW;
    // sP fill: 12 padded rows, strided pairs
    for (int idx = tid; idx < 12*32*32; idx += 512) {
        int r = idx >> 10;             // /1024
        int rem = idx & 1023;
        int i = rem >> 5, c = rem & 31;
        int sr = m60(p0 + r);
        const float* src = AbB + (size_t)sFm[i]*HW + sr*56;
        sP[idx] = pack2(src[m60(c)], src[m60(c + 28)]);
    }
    __syncthreads();

    ull acc[2][14];
    #pragma unroll
    for (int ff = 0; ff < 2; ff++)
        #pragma unroll
        for (int j = 0; j < 14; j++) acc[ff][j] = 0ull;

    const float* W3b = g_W3 + (size_t)b*30720 + fp*12;
    int i0 = half*16;

    float wA[10], wB[10];
    ull v[18];

    #define LOADW(i_, u_, W) { \
        const float* _w = W3b + (size_t)((i_)*5 + (u_))*192; \
        float4 _a = *(const float4*)_w; \
        float4 _b = *(const float4*)(_w + 4); \
        float2 _c = *(const float2*)(_w + 8); \
        (W)[0]=_a.x; (W)[1]=_a.y; (W)[2]=_a.z; (W)[3]=_a.w; \
        (W)[4]=_b.x; (W)[5]=_b.y; (W)[6]=_b.z; (W)[7]=_b.w; \
        (W)[8]=_c.x; (W)[9]=_c.y; }
    #define LOADV(i_, u_) { \
        const ull* _vp = sP + (size_t)((pl + (u_))*32 + (i_))*32 + q0; \
        _Pragma("unroll") for (int _k = 0; _k < 9; _k++) { \
            ulonglong2 _t = *(const ulonglong2*)(_vp + 2*_k); \
            v[2*_k] = _t.x; v[2*_k+1] = _t.y; } }
    #define COMP(W) { \
        _Pragma("unroll") for (int _y = 0; _y < 5; _y++) { \
            float _w0 = (W)[_y], _w1 = (W)[5 + _y]; \
            ull _p0 = pack2(_w0, _w0), _p1 = pack2(_w1, _w1); \
            _Pragma("unroll") for (int _j = 0; _j < 14; _j++) { \
                ffma2(acc[0][_j], v[_j + _y], _p0); \
                ffma2(acc[1][_j], v[_j + _y], _p1); } } }

    LOADW(i0, 0, wA);
    #pragma unroll 1
    for (int ii = 0; ii < 16; ii += 2) {
        int i = i0 + ii;
        int inx = (ii == 14) ? i0 : (i + 2);   // dummy-safe final prefetch
        LOADW(i,   1, wB); LOADV(i,   0); COMP(wA);
        LOADW(i,   2, wA); LOADV(i,   1); COMP(wB);
        LOADW(i,   3, wB); LOADV(i,   2); COMP(wA);
        LOADW(i,   4, wA); LOADV(i,   3); COMP(wB);
        LOADW(i+1, 0, wB); LOADV(i,   4); COMP(wA);
        LOADW(i+1, 1, wA); LOADV(i+1, 0); COMP(wB);
        LOADW(i+1, 2, wB); LOADV(i+1, 1); COMP(wA);
        LOADW(i+1, 3, wA); LOADV(i+1, 2); COMP(wB);
        LOADW(i+1, 4, wB); LOADV(i+1, 3); COMP(wA);
        LOADW(inx, 0, wA); LOADV(i+1, 4); COMP(wB);
    }
    #undef LOADW
    #undef LOADV
    #undef COMP

    // half 1 hands its partials to half 0
    if (half == 1) {
        ull* red = sRed + (size_t)t8*28;
        #pragma unroll
        for (int ff = 0; ff < 2; ff++)
            #pragma unroll
            for (int j = 0; j < 14; j++) red[ff*14 + j] = acc[ff][j];
    }
    __syncthreads();
    if (half == 0) {
        const ull* red = sRed + (size_t)t8*28;
        int p = p0 + pl;
        #pragma unroll
        for (int ff = 0; ff < 2; ff++) {
            int f = 2*fp + ff;
            const float* ar = AbB + (size_t)sFm[f]*HW + p*56;
            float* orow = out + ((size_t)(b*FM + f)*56 + p)*56;
            #pragma unroll
            for (int j = 0; j < 14; j++) {
                float2 vv = unpk(acc[ff][j]);
                float2 rr = unpk(red[ff*14 + j]);
                vv.x += rr.x; vv.y += rr.y;
                orow[q0 + j]      = ar[q0 + j]      + THETA_ * (vv.x * (1.f/32.f));
                orow[q0 + 28 + j] = ar[q0 + 28 + j] + THETA_ * (vv.y * (1.f/32.f));
            }
        }
    }
}

// ---------------- launch ----------------
extern "C" void kernel_launch(void* const* d_in, const int* in_sizes, int n_in,
                              void* d_out, int out_size) {
    const float* A     = (const float*)d_in[0];
    const float* K     = (const float*)d_in[1];
    const float* noise = (const float*)d_in[2];
    float* out = (float*)d_out;

    k_prep<<<BB*CC, 224>>>(A, noise);

    cudaFuncSetAttribute(k_kch, cudaFuncAttributeMaxDynamicSharedMemorySize, SMEM_KCH);
    k_kch<<<dim3(BB, 2, 4), 256, SMEM_KCH>>>();

    k_w2<<<128, 128>>>(K);
    k_gw<<<dim3(120, BB), 256>>>();

    cudaFuncSetAttribute(k_out, cudaFuncAttributeMaxDynamicSharedMemorySize, SMEM_OUT);
    k_out<<<dim3(BB, 7), 512, SMEM_OUT>>>(out);
}